// round 5
// baseline (speedup 1.0000x reference)
#include <cuda_runtime.h>

#define NPTS  1024
#define BTOT  32
#define RESV  48
#define SPIX  (RESV*RESV)
#define TILES 8
#define TROWS 6
#define NBINS 8
#define CAP   768            // per-(batch,rowtile) strip capacity
#define CAPC  513            // per col-bin capacity (padded: bank-offset between bins)

// global scratch (no allocations allowed)
__device__ float4 g_strip[BTOT * TILES * CAP];   // (X, Y, f_second, f_max), index-ordered
__device__ int    g_cnt[BTOT * TILES];

// ---------------------------------------------------------------------------
// Kernel 1: 32 blocks x 1024 threads, 1 point/thread.
// Projection + top-2 feats + block minmax + normalize + ordered scatter into
// the <=2 row-tile strips whose x-band (6t-2, 6t+7) contains X.
// ---------------------------------------------------------------------------
__global__ void __launch_bounds__(1024)
prep_kernel(const float* __restrict__ xyz,
            const float* __restrict__ feats,
            const float* __restrict__ theta,
            const float* __restrict__ phi)
{
    __shared__ float red[32 * 4];
    __shared__ int   wcnt[TILES * 32];
    __shared__ int   wbase[TILES * 32];

    int b = blockIdx.x;
    int k = b >> 2, m = b & 3;
    int tid = threadIdx.x, lane = tid & 31, wid = tid >> 5;

    float th = theta[m], ph = phi[m];
    float st = sinf(th), ct = cosf(th);
    float sp = sinf(ph), cp = cosf(ph);
    float U0 = -st, U1 = ct;
    float V0 = ct * sp, V1 = st * sp, V2 = cp;
    float cx = ct * cp, cy = st * cp, cz = sp;

    int g = k * NPTS + tid;
    float x = xyz[3 * g + 0];
    float y = xyz[3 * g + 1];
    float z = xyz[3 * g + 2];
    float dx = x - cx, dy = y - cy, dz = z - cz;
    float c0 = dx * U0 + dy * U1;
    float c1 = dx * V0 + dy * V1 + dz * V2;

    // top-2 of 20 (ascending last two of sort: [second, max])
    const float4* fr = (const float4*)(feats + (size_t)g * 20);
    float t1 = -1e30f, t2 = -1e30f;
#pragma unroll
    for (int q = 0; q < 5; q++) {
        float4 v = fr[q];
        float f;
        f = v.x; if (f > t1) { t2 = t1; t1 = f; } else if (f > t2) t2 = f;
        f = v.y; if (f > t1) { t2 = t1; t1 = f; } else if (f > t2) t2 = f;
        f = v.z; if (f > t1) { t2 = t1; t1 = f; } else if (f > t2) t2 = f;
        f = v.w; if (f > t1) { t2 = t1; t1 = f; } else if (f > t2) t2 = f;
    }

    // block minmax (order-invariant, exact)
    float mn0 = c0, mx0 = c0, mn1 = c1, mx1 = c1;
#pragma unroll
    for (int o = 16; o > 0; o >>= 1) {
        mn0 = fminf(mn0, __shfl_xor_sync(0xffffffffu, mn0, o));
        mx0 = fmaxf(mx0, __shfl_xor_sync(0xffffffffu, mx0, o));
        mn1 = fminf(mn1, __shfl_xor_sync(0xffffffffu, mn1, o));
        mx1 = fmaxf(mx1, __shfl_xor_sync(0xffffffffu, mx1, o));
    }
    if (lane == 0) {
        red[wid] = mn0; red[32 + wid] = mx0;
        red[64 + wid] = mn1; red[96 + wid] = mx1;
    }
    __syncthreads();
    mn0 = red[0]; mx0 = red[32]; mn1 = red[64]; mx1 = red[96];
#pragma unroll
    for (int w = 1; w < 32; w++) {
        mn0 = fminf(mn0, red[w]);      mx0 = fmaxf(mx0, red[32 + w]);
        mn1 = fminf(mn1, red[64 + w]); mx1 = fmaxf(mx1, red[96 + w]);
    }
    float ctr0 = (mx0 + mn0) * 0.5f;
    float ctr1 = (mx1 + mn1) * 0.5f;
    float sc0  = fmaxf(mx0 - mn0, 1e-5f) * 0.5f;
    float sc1  = fmaxf(mx1 - mn1, 1e-5f) * 0.5f;

    float X = (__fdiv_rn(c0 - ctr0, sc0) + 1.0f) * 19.2f + 4.8f;
    float Y = (__fdiv_rn(c1 - ctr1, sc1) + 1.0f) * 19.2f + 4.8f;

    // row-tile band ballots
    unsigned bal[TILES];
#pragma unroll
    for (int t = 0; t < TILES; t++) {
        bool kk = (X > (float)(TROWS * t) - 2.0f) &&
                  (X < (float)(TROWS * t + TROWS - 1) + 2.0f);
        bal[t] = __ballot_sync(0xffffffffu, kk);
        if (lane == 0) wcnt[t * 32 + wid] = __popc(bal[t]);
    }
    __syncthreads();

    // warp t scans 32 warp-counts for tile t
    if (wid < TILES) {
        int v = wcnt[wid * 32 + lane];
        int incl = v;
#pragma unroll
        for (int o = 1; o < 32; o <<= 1) {
            int n = __shfl_up_sync(0xffffffffu, incl, o);
            if (lane >= o) incl += n;
        }
        wbase[wid * 32 + lane] = incl - v;
        if (lane == 31) g_cnt[b * TILES + wid] = incl;
    }
    __syncthreads();

    // ordered scatter (<=2 tiles per point)
    unsigned lmask = (1u << lane) - 1u;
    float4 rec = make_float4(X, Y, t2, t1);
#pragma unroll
    for (int t = 0; t < TILES; t++) {
        if ((bal[t] >> lane) & 1u) {
            int idx = wbase[t * 32 + wid] + __popc(bal[t] & lmask);
            if (idx < CAP) g_strip[(b * TILES + t) * CAP + idx] = rec;
        }
    }
}

// ---------------------------------------------------------------------------
// Kernel 2: grid (8, 32), 288 threads (9 warps); 6 rows x 48 cols pixels.
// Ordered col-bin scatter of the strip list into shared, then ball query
// with exact warp-uniform early exit (first-16 semantics preserved).
// ---------------------------------------------------------------------------
#define SMEM2 68000
extern __shared__ char smem_raw[];

__global__ void __launch_bounds__(288)
mask_kernel(float* __restrict__ out)
{
    float4*   bins   = (float4*)(smem_raw);
    int*      cnt2   = (int*)(smem_raw + 65664);
    unsigned* bal2   = (unsigned*)(smem_raw + 66432);
    int*      sbase  = (int*)(smem_raw + 67200);
    int*      bintot = (int*)(smem_raw + 67968);

    int t = blockIdx.x, b = blockIdx.y;
    int tid = threadIdx.x, lane = tid & 31, wid = tid >> 5;

    int total = min(g_cnt[b * TILES + t], CAP);
    const float4* strip = g_strip + (b * TILES + t) * CAP;

    // --- ballot phase: 3 rounds x 256 threads, index-ordered ---
    float4 rv[3];
    if (wid < 8) {
#pragma unroll
        for (int q = 0; q < 3; q++) {
            int pos = q * 256 + wid * 32 + lane;
            bool valid = pos < total;
            rv[q] = valid ? strip[pos] : make_float4(-100.f, -100.f, 0.f, 0.f);
#pragma unroll
            for (int c = 0; c < NBINS; c++) {
                bool kk = valid &&
                          (rv[q].y > (float)(TROWS * c) - 2.0f) &&
                          (rv[q].y < (float)(TROWS * c + TROWS - 1) + 2.0f);
                unsigned ba = __ballot_sync(0xffffffffu, kk);
                if (lane == 0) {
                    bal2[c * 24 + q * 8 + wid] = ba;
                    cnt2[c * 24 + q * 8 + wid] = __popc(ba);
                }
            }
        }
    }
    __syncthreads();

    // --- scan phase: warp c scans its 24 (round,warp) counts ---
    if (wid < NBINS) {
        int v = (lane < 24) ? cnt2[wid * 24 + lane] : 0;
        int incl = v;
#pragma unroll
        for (int o = 1; o < 32; o <<= 1) {
            int n = __shfl_up_sync(0xffffffffu, incl, o);
            if (lane >= o) incl += n;
        }
        if (lane < 24) sbase[wid * 24 + lane] = incl - v;
        if (lane == 23) bintot[wid] = incl;
    }
    __syncthreads();

    // --- ordered scatter into col bins ---
    if (wid < 8) {
        unsigned lmask = (1u << lane) - 1u;
#pragma unroll
        for (int q = 0; q < 3; q++) {
#pragma unroll
            for (int c = 0; c < NBINS; c++) {
                unsigned ba = bal2[c * 24 + q * 8 + wid];
                if ((ba >> lane) & 1u) {
                    int idx = sbase[c * 24 + q * 8 + wid] + __popc(ba & lmask);
                    if (idx < CAPC) bins[c * CAPC + idx] = rv[q];
                }
            }
        }
    }
    __syncthreads();

    // --- per-pixel ball query: first 16 in index order with d2 < 4 ---
    int row = tid / RESV;
    int j   = tid - row * RESV;
    int i   = t * TROWS + row;
    int c   = j / TROWS;
    int tot = min(bintot[c], CAPC);
    const float4* bp = bins + c * CAPC;

    float sx = (float)i, sy = (float)j;
    int nsel = 0;
    float f0 = 0.0f, f1 = 0.0f;

    // Chunked loop with exact early exit: once nsel==16, later points can
    // never be selected (first-16-in-index-order), so breaking is bit-exact.
    for (int p0 = 0; ; p0 += 8) {
#pragma unroll
        for (int u = 0; u < 8; u++) {
            int p = p0 + u;
            bool live = (p < tot) & (nsel < 16);
            float4 q;
            if (live) {
                q = bp[p];
                float ddx = sx - q.x;
                float ddy = sy - q.y;
                float d2 = fmaf(ddx, ddx, ddy * ddy);
                if (d2 < 4.0f) { f0 += q.z; f1 += q.w; nsel++; }
            }
        }
        if (__all_sync(0xffffffffu, (p0 + 8 >= tot) | (nsel >= 16))) break;
    }

    float occ = fmaxf((float)nsel, 1.0f);
    float a0 = __fdiv_rn(f0, occ);
    float a1 = __fdiv_rn(f1, occ);
    float mxv = fmaxf(a0, a1);
    float e0 = expf(a0 - mxv);
    float e1 = expf(a1 - mxv);
    float s  = e0 + e1;
    float nf0 = __fdiv_rn(e0, s);
    float nf1 = __fdiv_rn(e1, s);
    float v = (nf0 == nf1) ? 0.0f : nf1 * 255.0f;

    int base = (b * 3) * SPIX + i * RESV + j;
    out[base]            = v;
    out[base + SPIX]     = v;
    out[base + 2 * SPIX] = v;
}

extern "C" void kernel_launch(void* const* d_in, const int* in_sizes, int n_in,
                              void* d_out, int out_size)
{
    const float* xyz   = (const float*)d_in[0];
    const float* feats = (const float*)d_in[1];
    const float* theta = (const float*)d_in[n_in - 2];
    const float* phi   = (const float*)d_in[n_in - 1];
    float* out = (float*)d_out;

    cudaFuncSetAttribute(mask_kernel,
                         cudaFuncAttributeMaxDynamicSharedMemorySize, SMEM2);

    prep_kernel<<<BTOT, 1024>>>(xyz, feats, theta, phi);
    mask_kernel<<<dim3(TILES, BTOT), 288, SMEM2>>>(out);
}

// round 6
// speedup vs baseline: 1.3241x; 1.3241x over previous
#include <cuda_runtime.h>

#define NPTS  1024
#define BTOT  32
#define RESV  48
#define SPIX  (RESV*RESV)
#define TILES 8
#define TROWS 6
#define NBINS 8
#define CAP   768            // per-(batch,rowtile) strip capacity
#define CAPC  513            // per col-bin capacity (padded: bank-offset between bins)

// global scratch (no allocations allowed)
__device__ float4 g_strip[BTOT * TILES * CAP];   // (X, Y, f_second, f_max), index-ordered
__device__ int    g_cnt[BTOT * TILES];

// ---------------------------------------------------------------------------
// Kernel 1: 32 blocks x 1024 threads, 1 point/thread.
// ---------------------------------------------------------------------------
__global__ void __launch_bounds__(1024)
prep_kernel(const float* __restrict__ xyz,
            const float* __restrict__ feats,
            const float* __restrict__ theta,
            const float* __restrict__ phi)
{
    __shared__ float red[32 * 4];
    __shared__ int   wcnt[TILES * 32];
    __shared__ int   wbase[TILES * 32];

    int b = blockIdx.x;
    int k = b >> 2, m = b & 3;
    int tid = threadIdx.x, lane = tid & 31, wid = tid >> 5;

    float th = theta[m], ph = phi[m];
    float st = sinf(th), ct = cosf(th);
    float sp = sinf(ph), cp = cosf(ph);
    float U0 = -st, U1 = ct;
    float V0 = ct * sp, V1 = st * sp, V2 = cp;
    float cx = ct * cp, cy = st * cp, cz = sp;

    int g = k * NPTS + tid;
    float x = xyz[3 * g + 0];
    float y = xyz[3 * g + 1];
    float z = xyz[3 * g + 2];
    float dx = x - cx, dy = y - cy, dz = z - cz;
    float c0 = dx * U0 + dy * U1;
    float c1 = dx * V0 + dy * V1 + dz * V2;

    // top-2 of 20 (ascending last two of sort: [second, max])
    const float4* fr = (const float4*)(feats + (size_t)g * 20);
    float t1 = -1e30f, t2 = -1e30f;
#pragma unroll
    for (int q = 0; q < 5; q++) {
        float4 v = fr[q];
        float f;
        f = v.x; if (f > t1) { t2 = t1; t1 = f; } else if (f > t2) t2 = f;
        f = v.y; if (f > t1) { t2 = t1; t1 = f; } else if (f > t2) t2 = f;
        f = v.z; if (f > t1) { t2 = t1; t1 = f; } else if (f > t2) t2 = f;
        f = v.w; if (f > t1) { t2 = t1; t1 = f; } else if (f > t2) t2 = f;
    }

    // block minmax (order-invariant, exact)
    float mn0 = c0, mx0 = c0, mn1 = c1, mx1 = c1;
#pragma unroll
    for (int o = 16; o > 0; o >>= 1) {
        mn0 = fminf(mn0, __shfl_xor_sync(0xffffffffu, mn0, o));
        mx0 = fmaxf(mx0, __shfl_xor_sync(0xffffffffu, mx0, o));
        mn1 = fminf(mn1, __shfl_xor_sync(0xffffffffu, mn1, o));
        mx1 = fmaxf(mx1, __shfl_xor_sync(0xffffffffu, mx1, o));
    }
    if (lane == 0) {
        red[wid] = mn0; red[32 + wid] = mx0;
        red[64 + wid] = mn1; red[96 + wid] = mx1;
    }
    __syncthreads();
    mn0 = red[0]; mx0 = red[32]; mn1 = red[64]; mx1 = red[96];
#pragma unroll
    for (int w = 1; w < 32; w++) {
        mn0 = fminf(mn0, red[w]);      mx0 = fmaxf(mx0, red[32 + w]);
        mn1 = fminf(mn1, red[64 + w]); mx1 = fmaxf(mx1, red[96 + w]);
    }
    float ctr0 = (mx0 + mn0) * 0.5f;
    float ctr1 = (mx1 + mn1) * 0.5f;
    float sc0  = fmaxf(mx0 - mn0, 1e-5f) * 0.5f;
    float sc1  = fmaxf(mx1 - mn1, 1e-5f) * 0.5f;

    float X = (__fdiv_rn(c0 - ctr0, sc0) + 1.0f) * 19.2f + 4.8f;
    float Y = (__fdiv_rn(c1 - ctr1, sc1) + 1.0f) * 19.2f + 4.8f;

    // row-tile band ballots
    unsigned bal[TILES];
#pragma unroll
    for (int t = 0; t < TILES; t++) {
        bool kk = (X > (float)(TROWS * t) - 2.0f) &&
                  (X < (float)(TROWS * t + TROWS - 1) + 2.0f);
        bal[t] = __ballot_sync(0xffffffffu, kk);
        if (lane == 0) wcnt[t * 32 + wid] = __popc(bal[t]);
    }
    __syncthreads();

    // warp t scans 32 warp-counts for tile t
    if (wid < TILES) {
        int v = wcnt[wid * 32 + lane];
        int incl = v;
#pragma unroll
        for (int o = 1; o < 32; o <<= 1) {
            int n = __shfl_up_sync(0xffffffffu, incl, o);
            if (lane >= o) incl += n;
        }
        wbase[wid * 32 + lane] = incl - v;
        if (lane == 31) g_cnt[b * TILES + wid] = incl;
    }
    __syncthreads();

    // ordered scatter (<=2 tiles per point)
    unsigned lmask = (1u << lane) - 1u;
    float4 rec = make_float4(X, Y, t2, t1);
#pragma unroll
    for (int t = 0; t < TILES; t++) {
        if ((bal[t] >> lane) & 1u) {
            int idx = wbase[t * 32 + wid] + __popc(bal[t] & lmask);
            if (idx < CAP) g_strip[(b * TILES + t) * CAP + idx] = rec;
        }
    }
}

// ---------------------------------------------------------------------------
// Kernel 2: grid (8, 32), 288 threads (9 warps); 6 rows x 48 cols pixels.
// Ordered col-bin scatter + sentinel tail padding, then ball query with
// unconditional chunk loads (full MLP) + exact warp-uniform early exit.
// ---------------------------------------------------------------------------
#define SMEM2 68000
extern __shared__ char smem_raw[];

__global__ void __launch_bounds__(288)
mask_kernel(float* __restrict__ out)
{
    float4*   bins   = (float4*)(smem_raw);
    int*      cnt2   = (int*)(smem_raw + 65664);
    unsigned* bal2   = (unsigned*)(smem_raw + 66432);
    int*      sbase  = (int*)(smem_raw + 67200);
    int*      bintot = (int*)(smem_raw + 67968);

    int t = blockIdx.x, b = blockIdx.y;
    int tid = threadIdx.x, lane = tid & 31, wid = tid >> 5;

    int total = min(g_cnt[b * TILES + t], CAP);
    const float4* strip = g_strip + (b * TILES + t) * CAP;

    // --- ballot phase: 3 rounds x 256 threads, index-ordered ---
    float4 rv[3];
    if (wid < 8) {
#pragma unroll
        for (int q = 0; q < 3; q++) {
            int pos = q * 256 + wid * 32 + lane;
            bool valid = pos < total;
            rv[q] = valid ? strip[pos] : make_float4(-100.f, -100.f, 0.f, 0.f);
#pragma unroll
            for (int c = 0; c < NBINS; c++) {
                bool kk = valid &&
                          (rv[q].y > (float)(TROWS * c) - 2.0f) &&
                          (rv[q].y < (float)(TROWS * c + TROWS - 1) + 2.0f);
                unsigned ba = __ballot_sync(0xffffffffu, kk);
                if (lane == 0) {
                    bal2[c * 24 + q * 8 + wid] = ba;
                    cnt2[c * 24 + q * 8 + wid] = __popc(ba);
                }
            }
        }
    }
    __syncthreads();

    // --- scan phase: warp c scans its 24 (round,warp) counts ---
    if (wid < NBINS) {
        int v = (lane < 24) ? cnt2[wid * 24 + lane] : 0;
        int incl = v;
#pragma unroll
        for (int o = 1; o < 32; o <<= 1) {
            int n = __shfl_up_sync(0xffffffffu, incl, o);
            if (lane >= o) incl += n;
        }
        if (lane < 24) sbase[wid * 24 + lane] = incl - v;
        if (lane == 23) bintot[wid] = incl;
    }
    __syncthreads();

    // --- ordered scatter into col bins; warp 8 pads tails with sentinels ---
    if (wid < 8) {
        unsigned lmask = (1u << lane) - 1u;
#pragma unroll
        for (int q = 0; q < 3; q++) {
#pragma unroll
            for (int c = 0; c < NBINS; c++) {
                unsigned ba = bal2[c * 24 + q * 8 + wid];
                if ((ba >> lane) & 1u) {
                    int idx = sbase[c * 24 + q * 8 + wid] + __popc(ba & lmask);
                    if (idx < CAPC) bins[c * CAPC + idx] = rv[q];
                }
            }
        }
    } else {
        // lanes 0..7 each pad one bin's tail up to the next multiple of 8
        if (lane < NBINS) {
            int c   = lane;
            int bt  = min(bintot[c], 512);         // clamp keeps pads < CAPC
            int bt8 = (bt + 7) & ~7;
            float4 sent = make_float4(-100.f, -100.f, 0.f, 0.f);
            for (int p = bt; p < bt8; p++)
                bins[c * CAPC + p] = sent;
        }
    }
    __syncthreads();

    // --- per-pixel ball query: first 16 in index order with d2 < 4 ---
    int row = tid / RESV;
    int j   = tid - row * RESV;
    int i   = t * TROWS + row;
    int c   = j / TROWS;
    int tot  = min(bintot[c], 512);
    int tot8 = (tot + 7) & ~7;
    const float4* bp = bins + c * CAPC;

    float sx = (float)i, sy = (float)j;
    int nsel = 0;
    float f0 = 0.0f, f1 = 0.0f;

    for (int p0 = 0; p0 < tot8; p0 += 8) {
        // unconditional loads: 8 independent LDS.128 in flight
        float4 q0 = bp[p0 + 0], q1 = bp[p0 + 1], q2 = bp[p0 + 2], q3 = bp[p0 + 3];
        float4 q4 = bp[p0 + 4], q5 = bp[p0 + 5], q6 = bp[p0 + 6], q7 = bp[p0 + 7];
        float d2_0, d2_1, d2_2, d2_3, d2_4, d2_5, d2_6, d2_7;
        { float a = sx - q0.x, bb = sy - q0.y; d2_0 = fmaf(a, a, bb * bb); }
        { float a = sx - q1.x, bb = sy - q1.y; d2_1 = fmaf(a, a, bb * bb); }
        { float a = sx - q2.x, bb = sy - q2.y; d2_2 = fmaf(a, a, bb * bb); }
        { float a = sx - q3.x, bb = sy - q3.y; d2_3 = fmaf(a, a, bb * bb); }
        { float a = sx - q4.x, bb = sy - q4.y; d2_4 = fmaf(a, a, bb * bb); }
        { float a = sx - q5.x, bb = sy - q5.y; d2_5 = fmaf(a, a, bb * bb); }
        { float a = sx - q6.x, bb = sy - q6.y; d2_6 = fmaf(a, a, bb * bb); }
        { float a = sx - q7.x, bb = sy - q7.y; d2_7 = fmaf(a, a, bb * bb); }
        // serial selection chain (cheap ALU; sentinels have d2 ~ 1.2e4)
        if (d2_0 < 4.0f && nsel < 16) { f0 += q0.z; f1 += q0.w; nsel++; }
        if (d2_1 < 4.0f && nsel < 16) { f0 += q1.z; f1 += q1.w; nsel++; }
        if (d2_2 < 4.0f && nsel < 16) { f0 += q2.z; f1 += q2.w; nsel++; }
        if (d2_3 < 4.0f && nsel < 16) { f0 += q3.z; f1 += q3.w; nsel++; }
        if (d2_4 < 4.0f && nsel < 16) { f0 += q4.z; f1 += q4.w; nsel++; }
        if (d2_5 < 4.0f && nsel < 16) { f0 += q5.z; f1 += q5.w; nsel++; }
        if (d2_6 < 4.0f && nsel < 16) { f0 += q6.z; f1 += q6.w; nsel++; }
        if (d2_7 < 4.0f && nsel < 16) { f0 += q7.z; f1 += q7.w; nsel++; }
        // exact early exit: once nsel==16 nothing later can be selected
        if (__all_sync(0xffffffffu, (p0 + 8 >= tot8) | (nsel >= 16))) break;
    }

    float occ = fmaxf((float)nsel, 1.0f);
    float a0 = __fdiv_rn(f0, occ);
    float a1 = __fdiv_rn(f1, occ);
    float mxv = fmaxf(a0, a1);
    float e0 = expf(a0 - mxv);
    float e1 = expf(a1 - mxv);
    float s  = e0 + e1;
    float nf0 = __fdiv_rn(e0, s);
    float nf1 = __fdiv_rn(e1, s);
    float v = (nf0 == nf1) ? 0.0f : nf1 * 255.0f;

    int base = (b * 3) * SPIX + i * RESV + j;
    out[base]            = v;
    out[base + SPIX]     = v;
    out[base + 2 * SPIX] = v;
}

extern "C" void kernel_launch(void* const* d_in, const int* in_sizes, int n_in,
                              void* d_out, int out_size)
{
    const float* xyz   = (const float*)d_in[0];
    const float* feats = (const float*)d_in[1];
    const float* theta = (const float*)d_in[n_in - 2];
    const float* phi   = (const float*)d_in[n_in - 1];
    float* out = (float*)d_out;

    cudaFuncSetAttribute(mask_kernel,
                         cudaFuncAttributeMaxDynamicSharedMemorySize, SMEM2);

    prep_kernel<<<BTOT, 1024>>>(xyz, feats, theta, phi);
    mask_kernel<<<dim3(TILES, BTOT), 288, SMEM2>>>(out);
}

// round 7
// speedup vs baseline: 1.3656x; 1.0313x over previous
#include <cuda_runtime.h>

#define NPTS  1024
#define BTOT  32
#define RESV  48
#define SPIX  (RESV*RESV)
#define TILES 8
#define TROWS 6
#define CAP   768            // per-(batch,rowtile) strip capacity

#define NSUB  3              // 2-row sub-strips per tile
#define NCB   8              // col bins (6 cols each)
#define NBIN2 (NSUB*NCB)     // 24 bins
#define CAPB  256            // per-bin capacity
#define BSTR  264            // bin stride (floats4); loads up to CAPB-1+7 stay inside

// global scratch (no allocations allowed)
__device__ float4 g_strip[BTOT * TILES * CAP];   // (X,Y,f_second,f_max), index-ordered
__device__ int    g_cnt[BTOT * TILES];

// exact membership conditions (MUST be identical in ballot + scatter)
__device__ __forceinline__ bool sub_cond(float X, int t, int s) {
    int r0 = TROWS * t + 2 * s;
    return (X > (float)r0 - 2.0f) && (X < (float)(r0 + 1) + 2.0f);
}
__device__ __forceinline__ bool col_cond(float Y, int c) {
    return (Y > (float)(TROWS * c) - 2.0f) && (Y < (float)(TROWS * c + TROWS - 1) + 2.0f);
}

// ---------------------------------------------------------------------------
// Kernel 1: 32 blocks x 1024 threads, 1 point/thread. (unchanged from R6)
// ---------------------------------------------------------------------------
__global__ void __launch_bounds__(1024)
prep_kernel(const float* __restrict__ xyz,
            const float* __restrict__ feats,
            const float* __restrict__ theta,
            const float* __restrict__ phi)
{
    __shared__ float red[32 * 4];
    __shared__ int   wcnt[TILES * 32];
    __shared__ int   wbase[TILES * 32];

    int b = blockIdx.x;
    int k = b >> 2, m = b & 3;
    int tid = threadIdx.x, lane = tid & 31, wid = tid >> 5;

    float th = theta[m], ph = phi[m];
    float st = sinf(th), ct = cosf(th);
    float sp = sinf(ph), cp = cosf(ph);
    float U0 = -st, U1 = ct;
    float V0 = ct * sp, V1 = st * sp, V2 = cp;
    float cx = ct * cp, cy = st * cp, cz = sp;

    int g = k * NPTS + tid;
    float x = xyz[3 * g + 0];
    float y = xyz[3 * g + 1];
    float z = xyz[3 * g + 2];
    float dx = x - cx, dy = y - cy, dz = z - cz;
    float c0 = dx * U0 + dy * U1;
    float c1 = dx * V0 + dy * V1 + dz * V2;

    const float4* fr = (const float4*)(feats + (size_t)g * 20);
    float t1 = -1e30f, t2 = -1e30f;
#pragma unroll
    for (int q = 0; q < 5; q++) {
        float4 v = fr[q];
        float f;
        f = v.x; if (f > t1) { t2 = t1; t1 = f; } else if (f > t2) t2 = f;
        f = v.y; if (f > t1) { t2 = t1; t1 = f; } else if (f > t2) t2 = f;
        f = v.z; if (f > t1) { t2 = t1; t1 = f; } else if (f > t2) t2 = f;
        f = v.w; if (f > t1) { t2 = t1; t1 = f; } else if (f > t2) t2 = f;
    }

    float mn0 = c0, mx0 = c0, mn1 = c1, mx1 = c1;
#pragma unroll
    for (int o = 16; o > 0; o >>= 1) {
        mn0 = fminf(mn0, __shfl_xor_sync(0xffffffffu, mn0, o));
        mx0 = fmaxf(mx0, __shfl_xor_sync(0xffffffffu, mx0, o));
        mn1 = fminf(mn1, __shfl_xor_sync(0xffffffffu, mn1, o));
        mx1 = fmaxf(mx1, __shfl_xor_sync(0xffffffffu, mx1, o));
    }
    if (lane == 0) {
        red[wid] = mn0; red[32 + wid] = mx0;
        red[64 + wid] = mn1; red[96 + wid] = mx1;
    }
    __syncthreads();
    mn0 = red[0]; mx0 = red[32]; mn1 = red[64]; mx1 = red[96];
#pragma unroll
    for (int w = 1; w < 32; w++) {
        mn0 = fminf(mn0, red[w]);      mx0 = fmaxf(mx0, red[32 + w]);
        mn1 = fminf(mn1, red[64 + w]); mx1 = fmaxf(mx1, red[96 + w]);
    }
    float ctr0 = (mx0 + mn0) * 0.5f;
    float ctr1 = (mx1 + mn1) * 0.5f;
    float sc0  = fmaxf(mx0 - mn0, 1e-5f) * 0.5f;
    float sc1  = fmaxf(mx1 - mn1, 1e-5f) * 0.5f;

    float X = (__fdiv_rn(c0 - ctr0, sc0) + 1.0f) * 19.2f + 4.8f;
    float Y = (__fdiv_rn(c1 - ctr1, sc1) + 1.0f) * 19.2f + 4.8f;

    unsigned bal[TILES];
#pragma unroll
    for (int t = 0; t < TILES; t++) {
        bool kk = (X > (float)(TROWS * t) - 2.0f) &&
                  (X < (float)(TROWS * t + TROWS - 1) + 2.0f);
        bal[t] = __ballot_sync(0xffffffffu, kk);
        if (lane == 0) wcnt[t * 32 + wid] = __popc(bal[t]);
    }
    __syncthreads();

    if (wid < TILES) {
        int v = wcnt[wid * 32 + lane];
        int incl = v;
#pragma unroll
        for (int o = 1; o < 32; o <<= 1) {
            int n = __shfl_up_sync(0xffffffffu, incl, o);
            if (lane >= o) incl += n;
        }
        wbase[wid * 32 + lane] = incl - v;
        if (lane == 31) g_cnt[b * TILES + wid] = incl;
    }
    __syncthreads();

    unsigned lmask = (1u << lane) - 1u;
    float4 rec = make_float4(X, Y, t2, t1);
#pragma unroll
    for (int t = 0; t < TILES; t++) {
        if ((bal[t] >> lane) & 1u) {
            int idx = wbase[t * 32 + wid] + __popc(bal[t] & lmask);
            if (idx < CAP) g_strip[(b * TILES + t) * CAP + idx] = rec;
        }
    }
}

// ---------------------------------------------------------------------------
// Kernel 2: grid (8, 32), 288 threads (9 warps).
// 24 bins = 3 sub-strips (2 rows) x 8 col bins; factored ballots.
// dynamic smem layout (bytes):
//   [0, 101376)        float4 bins[24 * BSTR]
//   [101376, 101664)   uint balS[3][24]
//   [101664, 102432)   uint balC[8][24]
//   [102432, 104736)   int  sbase[24][24]
//   [104736, 104832)   int  bintot[24]
// ---------------------------------------------------------------------------
#define SMEM2 104832
extern __shared__ char smem_raw[];

__global__ void __launch_bounds__(288)
mask_kernel(float* __restrict__ out)
{
    float4*   bins   = (float4*)(smem_raw);
    unsigned* balS   = (unsigned*)(smem_raw + 101376);
    unsigned* balC   = (unsigned*)(smem_raw + 101664);
    int*      sbase  = (int*)(smem_raw + 102432);
    int*      bintot = (int*)(smem_raw + 104736);

    int t = blockIdx.x, b = blockIdx.y;
    int tid = threadIdx.x, lane = tid & 31, wid = tid >> 5;

    int total = min(g_cnt[b * TILES + t], CAP);
    const float4* strip = g_strip + (b * TILES + t) * CAP;

    // --- Phase 1: factored ballots (3 rounds x 256 threads, index-ordered) ---
    float4 rv[3]; bool rvalid[3];
    if (wid < 8) {
#pragma unroll
        for (int q = 0; q < 3; q++) {
            int pos = q * 256 + wid * 32 + lane;
            bool valid = pos < total;
            rvalid[q] = valid;
            rv[q] = valid ? strip[pos] : make_float4(-100.f, -100.f, 0.f, 0.f);
#pragma unroll
            for (int s = 0; s < NSUB; s++) {
                unsigned ba = __ballot_sync(0xffffffffu, valid && sub_cond(rv[q].x, t, s));
                if (lane == 0) balS[s * 24 + q * 8 + wid] = ba;
            }
#pragma unroll
            for (int c = 0; c < NCB; c++) {
                unsigned ba = __ballot_sync(0xffffffffu, valid && col_cond(rv[q].y, c));
                if (lane == 0) balC[c * 24 + q * 8 + wid] = ba;
            }
        }
    }
    __syncthreads();

    // --- Phase 2: per-bin scans (each warp handles bins wid, wid+9, wid+18) ---
    for (int bin = wid; bin < NBIN2; bin += 9) {
        int s = bin >> 3, c = bin & 7;
        int v = 0;
        if (lane < 24) v = __popc(balS[s * 24 + lane] & balC[c * 24 + lane]);
        int incl = v;
#pragma unroll
        for (int o = 1; o < 32; o <<= 1) {
            int n = __shfl_up_sync(0xffffffffu, incl, o);
            if (lane >= o) incl += n;
        }
        if (lane < 24) sbase[bin * 24 + lane] = incl - v;
        if (lane == 23) bintot[bin] = incl;
    }
    __syncthreads();

    // --- Phase 3: scatter (each thread writes its point to its <=6 bins) ---
    if (wid < 8) {
        unsigned lmask = (1u << lane) - 1u;
#pragma unroll
        for (int q = 0; q < 3; q++) {
            if (!rvalid[q]) continue;
            float X = rv[q].x, Y = rv[q].y;
            int cc0 = (int)(Y * (1.0f / 6.0f));   // candidates cc0-1..cc0+1
#pragma unroll
            for (int s = 0; s < NSUB; s++) {
                if (!sub_cond(X, t, s)) continue;
                unsigned bs = balS[s * 24 + q * 8 + wid];
#pragma unroll
                for (int dc = -1; dc <= 1; dc++) {
                    int c = cc0 + dc;
                    if (c < 0 || c >= NCB) continue;
                    if (!col_cond(Y, c)) continue;
                    unsigned ba = bs & balC[c * 24 + q * 8 + wid];
                    int bin = s * NCB + c;
                    int idx = sbase[bin * 24 + q * 8 + wid] + __popc(ba & lmask);
                    if (idx < CAPB) bins[bin * BSTR + idx] = rv[q];
                }
            }
        }
    }
    __syncthreads();

    // --- Phase 4: per-pixel ball query (first 16 in index order, d2 < 4) ---
    // warp w: sub-strip sr = w/3, col group cg = w%3 (16 cols)
    int sr = wid / 3, cg = wid - 3 * sr;
    int r  = lane >> 4, ccol = lane & 15;
    int i  = t * TROWS + 2 * sr + r;
    int j  = 16 * cg + ccol;
    int c  = j / TROWS;
    int bin = sr * NCB + c;
    int tot = min(bintot[bin], CAPB);
    const float4* bp = bins + bin * BSTR;

    int pmax = tot;
#pragma unroll
    for (int o = 16; o > 0; o >>= 1)
        pmax = max(pmax, __shfl_xor_sync(0xffffffffu, pmax, o));

    float sx = (float)i, sy = (float)j;
    int nsel = 0;
    float f0 = 0.0f, f1 = 0.0f;

    for (int p0 = 0; p0 < pmax; p0 += 8) {
        // unconditional loads (full MLP); addresses stay inside the bin slot
        float4 q0 = bp[p0 + 0], q1 = bp[p0 + 1], q2 = bp[p0 + 2], q3 = bp[p0 + 3];
        float4 q4 = bp[p0 + 4], q5 = bp[p0 + 5], q6 = bp[p0 + 6], q7 = bp[p0 + 7];
        float d0, d1, d2v, d3, d4, d5, d6, d7;
        { float a = sx - q0.x, bb = sy - q0.y; d0  = fmaf(a, a, bb * bb); }
        { float a = sx - q1.x, bb = sy - q1.y; d1  = fmaf(a, a, bb * bb); }
        { float a = sx - q2.x, bb = sy - q2.y; d2v = fmaf(a, a, bb * bb); }
        { float a = sx - q3.x, bb = sy - q3.y; d3  = fmaf(a, a, bb * bb); }
        { float a = sx - q4.x, bb = sy - q4.y; d4  = fmaf(a, a, bb * bb); }
        { float a = sx - q5.x, bb = sy - q5.y; d5  = fmaf(a, a, bb * bb); }
        { float a = sx - q6.x, bb = sy - q6.y; d6  = fmaf(a, a, bb * bb); }
        { float a = sx - q7.x, bb = sy - q7.y; d7  = fmaf(a, a, bb * bb); }
        // index guard p<tot is ALU-side (junk beyond tot predicated off)
        if (p0 + 0 < tot && d0  < 4.0f && nsel < 16) { f0 += q0.z; f1 += q0.w; nsel++; }
        if (p0 + 1 < tot && d1  < 4.0f && nsel < 16) { f0 += q1.z; f1 += q1.w; nsel++; }
        if (p0 + 2 < tot && d2v < 4.0f && nsel < 16) { f0 += q2.z; f1 += q2.w; nsel++; }
        if (p0 + 3 < tot && d3  < 4.0f && nsel < 16) { f0 += q3.z; f1 += q3.w; nsel++; }
        if (p0 + 4 < tot && d4  < 4.0f && nsel < 16) { f0 += q4.z; f1 += q4.w; nsel++; }
        if (p0 + 5 < tot && d5  < 4.0f && nsel < 16) { f0 += q5.z; f1 += q5.w; nsel++; }
        if (p0 + 6 < tot && d6  < 4.0f && nsel < 16) { f0 += q6.z; f1 += q6.w; nsel++; }
        if (p0 + 7 < tot && d7  < 4.0f && nsel < 16) { f0 += q7.z; f1 += q7.w; nsel++; }
        // exact early exit: once nsel==16 nothing later can be selected
        if (__all_sync(0xffffffffu, (p0 + 8 >= tot) | (nsel >= 16))) break;
    }

    float occ = fmaxf((float)nsel, 1.0f);
    float a0 = __fdiv_rn(f0, occ);
    float a1 = __fdiv_rn(f1, occ);
    float mxv = fmaxf(a0, a1);
    float e0 = expf(a0 - mxv);
    float e1 = expf(a1 - mxv);
    float s  = e0 + e1;
    float nf0 = __fdiv_rn(e0, s);
    float nf1 = __fdiv_rn(e1, s);
    float v = (nf0 == nf1) ? 0.0f : nf1 * 255.0f;

    int base = (b * 3) * SPIX + i * RESV + j;
    out[base]            = v;
    out[base + SPIX]     = v;
    out[base + 2 * SPIX] = v;
}

extern "C" void kernel_launch(void* const* d_in, const int* in_sizes, int n_in,
                              void* d_out, int out_size)
{
    const float* xyz   = (const float*)d_in[0];
    const float* feats = (const float*)d_in[1];
    const float* theta = (const float*)d_in[n_in - 2];
    const float* phi   = (const float*)d_in[n_in - 1];
    float* out = (float*)d_out;

    cudaFuncSetAttribute(mask_kernel,
                         cudaFuncAttributeMaxDynamicSharedMemorySize, SMEM2);

    prep_kernel<<<BTOT, 1024>>>(xyz, feats, theta, phi);
    mask_kernel<<<dim3(TILES, BTOT), 288, SMEM2>>>(out);
}